// round 15
// baseline (speedup 1.0000x reference)
#include <cuda_runtime.h>
#include <cuda_fp16.h>
#include <math.h>
#include <stdint.h>

// ---------------- problem constants ----------------
#define T_TOK 16384
#define DIM   2048
#define EXP   64
#define NTOT  128        // gate(64) + noise(64) outputs
#define NBLK  128        // CTAs, 128 tokens each
#define THREADS 512      // warps 0-7 scalar path, 8-15 tensor path
#define LPITCH 132
#define TIE_EPS 1e-3f

// K split: tensor path K in [0,768), scalar path K in [768,2048)
#define KT    32
#define NKT_T 24         // tensor tiles
#define NKT_S 40         // scalar tiles
#define KS_OFF 768

// smem layout (bytes)
//  scalar A: [2 buf][32 k][260 fl]  (duplicated pairs, pitch 1040B)
//  scalar B: [2 buf][32 k][132 fl]  (paired slots,     pitch 528B)
//  tensor A: [2 buf][2 term][128 r][80B]
//  tensor B: [2 buf][2 term][128 n][80B]
#define SA_OFF 0u
#define SA_BUF 33280u
#define SA_KP  1040u
#define SB_OFF 66560u
#define SB_BUF 16896u
#define SB_KP  528u
#define TA_OFF 100352u
#define T_BUF  20480u
#define T_TRM  10240u
#define TB_OFF 141312u
#define DYN_BYTES 182272

// ---------------- device scratch ----------------
__device__ __align__(16) __half g_Bh[2][NTOT * DIM];   // W split into 2 fp16 terms
__device__ float g_psum[NBLK * EXP];
__device__ float g_cnt [NBLK * EXP];

// ---------------- helpers ----------------
__device__ __forceinline__ uint32_t s2u(const void* p) {
    uint32_t a;
    asm("{ .reg .u64 t; cvta.to.shared.u64 t, %1; cvt.u32.u64 %0, t; }" : "=r"(a) : "l"(p));
    return a;
}
__device__ __forceinline__ uint32_t pack2h(__half a, __half b) {
    return (uint32_t)__half_as_ushort(a) | ((uint32_t)__half_as_ushort(b) << 16);
}
__device__ __forceinline__ unsigned long long dup2(float v) {
    unsigned long long r;
    asm("mov.b64 %0, {%1, %1};" : "=l"(r) : "f"(v));
    return r;
}
__device__ __forceinline__ void fma2(unsigned long long &d, unsigned long long a,
                                     unsigned long long b) {
    asm("fma.rn.f32x2 %0, %1, %2, %0;" : "+l"(d) : "l"(a), "l"(b));
}
__device__ __forceinline__ void mma16(float* c, const uint32_t* a, const uint32_t* b) {
    asm volatile(
        "mma.sync.aligned.m16n8k16.row.col.f32.f16.f16.f32 "
        "{%0,%1,%2,%3}, {%4,%5,%6,%7}, {%8,%9}, {%0,%1,%2,%3};"
        : "+f"(c[0]), "+f"(c[1]), "+f"(c[2]), "+f"(c[3])
        : "r"(a[0]), "r"(a[1]), "r"(a[2]), "r"(a[3]), "r"(b[0]), "r"(b[1]));
}
#define LDSM4(r, a) \
    asm volatile("ldmatrix.sync.aligned.m8n8.x4.shared.b16 {%0,%1,%2,%3}, [%4];" \
        : "=r"((r)[0]), "=r"((r)[1]), "=r"((r)[2]), "=r"((r)[3]) : "r"(a))
__device__ __forceinline__ void cp16(uint32_t s, const void* g) {
    asm volatile("cp.async.cg.shared.global [%0], [%1], 16;" :: "r"(s), "l"(g));
}
__device__ __forceinline__ float softplus_eps(float nv) {
    return fmaxf(nv, 0.f) + log1pf(expf(-fabsf(nv))) + 0.01f;
}
#define BAR_S() asm volatile("bar.sync 1, 256;" ::: "memory")
#define BAR_T() asm volatile("bar.sync 2, 256;" ::: "memory")

// profiler window shims (keep ncu -s5 -c1 slot on moe_kernel)
__global__ void shim1_kernel() {}
__global__ void shim2_kernel() {}

// ---------------- kernel 0: pre-split W into 2 fp16 terms ----------------
__global__ void splitW_kernel(const float* __restrict__ Wg, const float* __restrict__ Wn) {
    int idx = blockIdx.x * 256 + threadIdx.x;      // 0..262143 over [n][k]
    int n = idx >> 11, k = idx & 2047;
    float w = (n < 64) ? Wg[n * 2048 + k] : Wn[(n - 64) * 2048 + k];
    __half h0 = __float2half_rn(w);
    __half h1 = __float2half_rn(w - __half2float(h0));
    g_Bh[0][idx] = h0;
    g_Bh[1][idx] = h1;
}

// ---------------- kernel 1: hybrid scalar+tensor GEMM + fused epilogue ----------------
__global__ __launch_bounds__(THREADS, 1)
void moe_kernel(const float* __restrict__ x, const float* __restrict__ rn,
                const float* __restrict__ bg, const float* __restrict__ Wg,
                const float* __restrict__ Wn, float* __restrict__ out)
{
    extern __shared__ char dyn[];
    __shared__ float s_bg[EXP];
    __shared__ float m_s[128], is_s[128], p1_s[128];
    __shared__ int   hi_s[128], li_s[128];
    __shared__ int   s_flags[128];
    __shared__ int   s_nflag;
    __shared__ float s_resc[128];

    const int tid  = threadIdx.x;
    const int lane = tid & 31;

    if (tid < EXP) s_bg[tid] = bg[tid];
    if (tid == 0) s_nflag = 0;

    const int t0 = blockIdx.x * 128;
    const float* xb = x + (size_t)t0 * DIM;
    const uint32_t sd = s2u(dyn);
    float* sL = (float*)dyn;

    if (tid < 256) {
        // ================= SCALAR PATH (warps 0-7), K in [768,2048) =================
        const int tx = tid & 15;          // n octet
        const int ty = tid >> 4;          // m octet (0..15)
        // staging: thread -> row tid>>1, k-half (tid&1)*16
        const int srow = tid >> 1;
        const int skh  = (tid & 1) * 16;
        const int bn   = srow;            // B: n row, same k-half mapping
        const float* bsrc = (bn < 64) ? (Wg + (size_t)bn * DIM) : (Wn + (size_t)(bn - 64) * DIM);
        // B slot byte offset for paired layout: n -> ((j*16+tx)*2+e)*4
        const uint32_t bslot = (uint32_t)((((bn & 7) >> 1) * 16 + (bn >> 3)) * 2 + (bn & 1)) * 4u;

        unsigned long long c[8][4];
#pragma unroll
        for (int i = 0; i < 8; ++i)
#pragma unroll
            for (int j = 0; j < 4; ++j) c[i][j] = 0ull;

        float4 pf[4];
#define S_LDG_A(kb_) do {                                                      \
    const float* ap = xb + (size_t)srow * DIM + KS_OFF + (kb_) * KT + skh;     \
    pf[0] = *(const float4*)ap;       pf[1] = *(const float4*)(ap + 4);        \
    pf[2] = *(const float4*)(ap + 8); pf[3] = *(const float4*)(ap + 12);       \
} while (0)
#define S_STS_A(buf_) do {                                                     \
    uint32_t base = sd + SA_OFF + (buf_) * SA_BUF + (uint32_t)srow * 8u;       \
    _Pragma("unroll")                                                          \
    for (int q = 0; q < 4; ++q) {                                              \
        uint32_t kb0 = base + (uint32_t)(skh + q * 4) * SA_KP;                 \
        asm volatile("st.shared.b64 [%0], %1;" :: "r"(kb0),            "l"(dup2(pf[q].x))); \
        asm volatile("st.shared.b64 [%0], %1;" :: "r"(kb0 + SA_KP),    "l"(dup2(pf[q].y))); \
        asm volatile("st.shared.b64 [%0], %1;" :: "r"(kb0 + 2*SA_KP),  "l"(dup2(pf[q].z))); \
        asm volatile("st.shared.b64 [%0], %1;" :: "r"(kb0 + 3*SA_KP),  "l"(dup2(pf[q].w))); \
    }                                                                          \
} while (0)
#define S_LDG_B(kb_) do {                                                      \
    const float* bp = bsrc + KS_OFF + (kb_) * KT + skh;                        \
    pf[0] = *(const float4*)bp;       pf[1] = *(const float4*)(bp + 4);        \
    pf[2] = *(const float4*)(bp + 8); pf[3] = *(const float4*)(bp + 12);       \
} while (0)
#define S_STS_B(buf_) do {                                                     \
    uint32_t base = sd + SB_OFF + (buf_) * SB_BUF + bslot;                     \
    _Pragma("unroll")                                                          \
    for (int q = 0; q < 4; ++q) {                                              \
        uint32_t kb0 = base + (uint32_t)(skh + q * 4) * SB_KP;                 \
        asm volatile("st.shared.b32 [%0], %1;" :: "r"(kb0),           "f"(pf[q].x)); \
        asm volatile("st.shared.b32 [%0], %1;" :: "r"(kb0 + SB_KP),   "f"(pf[q].y)); \
        asm volatile("st.shared.b32 [%0], %1;" :: "r"(kb0 + 2*SB_KP), "f"(pf[q].z)); \
        asm volatile("st.shared.b32 [%0], %1;" :: "r"(kb0 + 3*SB_KP), "f"(pf[q].w)); \
    }                                                                          \
} while (0)
#define S_COMPUTE(buf_, klo, khi) do {                                         \
    uint32_t aB = sd + SA_OFF + (buf_) * SA_BUF + (uint32_t)(ty * 8) * 8u;     \
    uint32_t bB = sd + SB_OFF + (buf_) * SB_BUF + (uint32_t)tx * 8u;           \
    for (int k = (klo); k < (khi); ++k) {                                      \
        uint32_t ak = aB + (uint32_t)k * SA_KP;                                \
        uint32_t bk = bB + (uint32_t)k * SB_KP;                                \
        unsigned long long aa[8], bb[4];                                       \
        _Pragma("unroll")                                                      \
        for (int j = 0; j < 4; ++j)                                            \
            asm volatile("ld.shared.b64 %0, [%1];" : "=l"(bb[j]) : "r"(bk + j * 128u)); \
        _Pragma("unroll")                                                      \
        for (int i = 0; i < 8; ++i)                                            \
            asm volatile("ld.shared.b64 %0, [%1];" : "=l"(aa[i]) : "r"(ak + i * 8u)); \
        _Pragma("unroll")                                                      \
        for (int i = 0; i < 8; ++i) {                                          \
            fma2(c[i][0], aa[i], bb[0]); fma2(c[i][1], aa[i], bb[1]);          \
            fma2(c[i][2], aa[i], bb[2]); fma2(c[i][3], aa[i], bb[3]);          \
        }                                                                      \
    }                                                                          \
} while (0)

        S_LDG_A(0); S_STS_A(0);
        S_LDG_B(0); S_STS_B(0);
        BAR_S();
        for (int kb = 0; kb < NKT_S; ++kb) {
            const int buf = kb & 1;
            if (kb + 1 < NKT_S) S_LDG_A(kb + 1);
            S_COMPUTE(buf, 0, 16);
            if (kb + 1 < NKT_S) { S_STS_A(buf ^ 1); S_LDG_B(kb + 1); }
            S_COMPUTE(buf, 16, 32);
            if (kb + 1 < NKT_S) S_STS_B(buf ^ 1);
            BAR_S();
        }
        __syncthreads();                        // join both paths; smem now free
        // write scalar partial C
#pragma unroll
        for (int i = 0; i < 8; ++i)
#pragma unroll
            for (int j = 0; j < 4; ++j)
                *(unsigned long long*)&sL[(ty * 8 + i) * LPITCH + tx * 8 + 2 * j] = c[i][j];
        __syncthreads();
        __syncthreads();                        // tensor adds between these two
    } else {
        // ================= TENSOR PATH (warps 8-15), K in [0,768) =================
        const int wtid = tid - 256;
        const int wtw  = wtid >> 5;      // 0..7
        const int wm   = wtw & 1;
        const int wn4  = wtw >> 1;
        const int trow = wtid >> 1;
        const int tkh  = (wtid & 1) * 16;
        const int tbt  = wtid >> 7;      // B term
        const int tbn  = wtid & 127;     // B n row
        const uint32_t aLane = (uint32_t)(wm * 64 + (lane & 7) + ((lane >> 3) & 1) * 8) * 80u
                             + (uint32_t)((lane >> 4) & 1) * 16u;
        const uint32_t bLane = (uint32_t)(wn4 * 32 + (lane & 7) + ((lane >> 4) & 1) * 8) * 80u
                             + (uint32_t)((lane >> 3) & 1) * 16u;

        float c[4][4][4];
#pragma unroll
        for (int a = 0; a < 4; ++a)
#pragma unroll
            for (int b = 0; b < 4; ++b)
#pragma unroll
                for (int d = 0; d < 4; ++d) c[a][b][d] = 0.f;

        float4 tf[4];
#define T_LDG_A(kb_) do {                                                      \
    const float* ap = xb + (size_t)trow * DIM + (kb_) * KT + tkh;              \
    tf[0] = *(const float4*)ap;       tf[1] = *(const float4*)(ap + 4);        \
    tf[2] = *(const float4*)(ap + 8); tf[3] = *(const float4*)(ap + 12);       \
} while (0)
#define T_CVT_ST_A(buf_) do {                                                  \
    uint32_t h0[8], h1[8];                                                     \
    _Pragma("unroll")                                                          \
    for (int q = 0; q < 4; ++q) {                                              \
        float v0 = tf[q].x, v1 = tf[q].y, v2 = tf[q].z, v3 = tf[q].w;          \
        __half a0 = __float2half_rn(v0), a1 = __float2half_rn(v1);             \
        __half a2 = __float2half_rn(v2), a3 = __float2half_rn(v3);             \
        h0[q*2]   = pack2h(a0, a1); h0[q*2+1] = pack2h(a2, a3);                \
        h1[q*2]   = pack2h(__float2half_rn(v0 - __half2float(a0)),             \
                           __float2half_rn(v1 - __half2float(a1)));            \
        h1[q*2+1] = pack2h(__float2half_rn(v2 - __half2float(a2)),             \
                           __float2half_rn(v3 - __half2float(a3)));            \
    }                                                                          \
    uint32_t ad = sd + TA_OFF + (buf_) * T_BUF + (uint32_t)trow * 80u + tkh * 2u; \
    asm volatile("st.shared.v4.b32 [%0], {%1,%2,%3,%4};" :: "r"(ad),        "r"(h0[0]),"r"(h0[1]),"r"(h0[2]),"r"(h0[3])); \
    asm volatile("st.shared.v4.b32 [%0], {%1,%2,%3,%4};" :: "r"(ad + 16u),  "r"(h0[4]),"r"(h0[5]),"r"(h0[6]),"r"(h0[7])); \
    asm volatile("st.shared.v4.b32 [%0], {%1,%2,%3,%4};" :: "r"(ad + T_TRM),      "r"(h1[0]),"r"(h1[1]),"r"(h1[2]),"r"(h1[3])); \
    asm volatile("st.shared.v4.b32 [%0], {%1,%2,%3,%4};" :: "r"(ad + T_TRM + 16u),"r"(h1[4]),"r"(h1[5]),"r"(h1[6]),"r"(h1[7])); \
} while (0)
#define T_CPA_B(kb_, buf_) do {                                                \
    uint32_t bd = sd + TB_OFF + (buf_) * T_BUF + (uint32_t)tbt * T_TRM         \
                + (uint32_t)tbn * 80u;                                         \
    const __half* src = &g_Bh[tbt][(size_t)tbn * DIM + (kb_) * KT];            \
    cp16(bd,       src);      cp16(bd + 16u, src + 8);                         \
    cp16(bd + 32u, src + 16); cp16(bd + 48u, src + 24);                        \
    asm volatile("cp.async.commit_group;");                                    \
} while (0)
#define T_MMA_KS(ta_, tb_, ks_) do {                                           \
    uint32_t kofs = (uint32_t)(ks_) * 32u;                                     \
    uint32_t Af[4][4], B0[4][2], B1[4][2], bt[4];                              \
    _Pragma("unroll")                                                          \
    for (int mt = 0; mt < 4; ++mt) LDSM4(Af[mt], (ta_) + aLane + mt * 1280u + kofs); \
    LDSM4(bt, (tb_) + bLane + kofs);                                           \
    B0[0][0]=bt[0]; B0[0][1]=bt[1]; B0[1][0]=bt[2]; B0[1][1]=bt[3];            \
    LDSM4(bt, (tb_) + bLane + 1280u + kofs);                                   \
    B0[2][0]=bt[0]; B0[2][1]=bt[1]; B0[3][0]=bt[2]; B0[3][1]=bt[3];            \
    LDSM4(bt, (tb_) + T_TRM + bLane + kofs);                                   \
    B1[0][0]=bt[0]; B1[0][1]=bt[1]; B1[1][0]=bt[2]; B1[1][1]=bt[3];            \
    LDSM4(bt, (tb_) + T_TRM + bLane + 1280u + kofs);                           \
    B1[2][0]=bt[0]; B1[2][1]=bt[1]; B1[3][0]=bt[2]; B1[3][1]=bt[3];            \
    _Pragma("unroll")                                                          \
    for (int mt = 0; mt < 4; ++mt)                                             \
        _Pragma("unroll")                                                      \
        for (int nt = 0; nt < 4; ++nt) {                                       \
            mma16(c[mt][nt], Af[mt], B0[nt]);                                  \
            mma16(c[mt][nt], Af[mt], B1[nt]);                                  \
        }                                                                      \
    _Pragma("unroll")                                                          \
    for (int mt = 0; mt < 4; ++mt) LDSM4(Af[mt], (ta_) + T_TRM + aLane + mt * 1280u + kofs); \
    _Pragma("unroll")                                                          \
    for (int mt = 0; mt < 4; ++mt)                                             \
        _Pragma("unroll")                                                      \
        for (int nt = 0; nt < 4; ++nt)                                         \
            mma16(c[mt][nt], Af[mt], B0[nt]);                                  \
} while (0)

        T_CPA_B(0, 0);
        T_LDG_A(0); T_CVT_ST_A(0);
        asm volatile("cp.async.wait_group 0;");
        BAR_T();
        for (int kb = 0; kb < NKT_T; ++kb) {
            const int buf = kb & 1;
            if (kb + 1 < NKT_T) T_CPA_B(kb + 1, buf ^ 1);
            const uint32_t ta = sd + TA_OFF + buf * T_BUF;
            const uint32_t tb = sd + TB_OFF + buf * T_BUF;
            T_MMA_KS(ta, tb, 0);
            if (kb + 1 < NKT_T) T_LDG_A(kb + 1);
            T_MMA_KS(ta, tb, 1);
            if (kb + 1 < NKT_T) T_CVT_ST_A(buf ^ 1);
            asm volatile("cp.async.wait_group 0;");
            BAR_T();
        }
        __syncthreads();                        // join (scalar may still run its tail)
        __syncthreads();                        // scalar C now in sL
        // add tensor partial into sL
#pragma unroll
        for (int mt = 0; mt < 4; ++mt)
#pragma unroll
            for (int nt = 0; nt < 4; ++nt) {
                int row = wm * 64 + mt * 16 + (lane >> 2);
                int col = wn4 * 32 + nt * 8 + 2 * (lane & 3);
                sL[row * LPITCH + col]           += c[mt][nt][0];
                sL[row * LPITCH + col + 1]       += c[mt][nt][1];
                sL[(row + 8) * LPITCH + col]     += c[mt][nt][2];
                sL[(row + 8) * LPITCH + col + 1] += c[mt][nt][3];
            }
        __syncthreads();
    }
    __syncthreads();                            // sL complete for all

    // -------- phase 1: per-token epilogue (thread = token) --------
    if (tid < 128) {
        const int t = tid;
        const int tok = t0 + t;
        float* row = sL + t * LPITCH;
        float hv = -3.4e38f, lv = -3.4e38f, tv = -3.4e38f;
        int hi = 0, li = 0;
#pragma unroll 8
        for (int e = 0; e < 64; ++e) {
            float gg = row[e];
            float nv = row[64 + e];
            float v  = gg + s_bg[e] + rn[(size_t)tok * EXP + e] * softplus_eps(nv);
            row[e] = v;
            if (v > hv)      { tv = lv; lv = hv; li = hi; hv = v; hi = e; }
            else if (v > lv) { tv = lv; lv = v; li = e; }
            else if (v > tv) { tv = v; }
        }
        float ssum = 0.f;
#pragma unroll 8
        for (int e = 0; e < 64; ++e) ssum += expf(row[e] - hv);
        m_s[t] = hv; is_s[t] = 1.f / ssum; hi_s[t] = hi; li_s[t] = li;
        float ebt = expf(lv - hv);
        float den = 1.f / (1.f + ebt);
        float p0 = den, p1 = ebt * den;
        p1_s[t] = p1;
        float4 z = make_float4(0.f, 0.f, 0.f, 0.f);
        float4* orow = (float4*)(out + (size_t)tok * EXP);
#pragma unroll
        for (int q = 0; q < 16; ++q) orow[q] = z;
        out[(size_t)tok * EXP + hi] = p0;
        out[(size_t)tok * EXP + li] = p1;
        if (lv - tv < TIE_EPS) {
            int slot = atomicAdd(&s_nflag, 1);
            s_flags[slot] = t;
        }
    }
    __syncthreads();

    // -------- phase 2: exact fp32 rescue for near-tie tokens --------
    const int nflag = s_nflag;
    for (int f = 0; f < nflag; ++f) {
        const int t = s_flags[f];
        const int tok = t0 + t;
        if (tid < 128) {
            const int e = tid & 63;
            const float* wr = (tid < 64) ? (Wg + (size_t)e * DIM) : (Wn + (size_t)e * DIM);
            const float* xr = x + (size_t)tok * DIM;
            float a0 = 0.f, a1 = 0.f, a2 = 0.f, a3 = 0.f;
            for (int k = 0; k < DIM; k += 4) {
                float4 xv = *(const float4*)(xr + k);
                float4 wv = *(const float4*)(wr + k);
                a0 = fmaf(xv.x, wv.x, a0); a1 = fmaf(xv.y, wv.y, a1);
                a2 = fmaf(xv.z, wv.z, a2); a3 = fmaf(xv.w, wv.w, a3);
            }
            s_resc[tid] = (a0 + a1) + (a2 + a3);
        }
        __syncthreads();
        if (tid < 64) {
            float gg = s_resc[tid] + s_bg[tid];
            float nv = s_resc[64 + tid];
            sL[t * LPITCH + tid] = gg + rn[(size_t)tok * EXP + tid] * softplus_eps(nv);
        }
        __syncthreads();
        if (tid == 0) {
            float* row = sL + t * LPITCH;
            float hv = -3.4e38f, lv = -3.4e38f;
            int hi = 0, li = 0;
            for (int e = 0; e < 64; ++e) {
                float v = row[e];
                if (v > hv)      { lv = hv; li = hi; hv = v; hi = e; }
                else if (v > lv) { lv = v; li = e; }
            }
            float ssum = 0.f;
            for (int e = 0; e < 64; ++e) ssum += expf(row[e] - hv);
            m_s[t] = hv; is_s[t] = 1.f / ssum; hi_s[t] = hi; li_s[t] = li;
            float ebt = expf(lv - hv);
            float den = 1.f / (1.f + ebt);
            float p0 = den, p1 = ebt * den;
            p1_s[t] = p1;
            float* orow = out + (size_t)tok * EXP;
            for (int e = 0; e < 64; ++e) orow[e] = 0.f;
            orow[hi] = p0;
            orow[li] = p1;
        }
        __syncthreads();
    }

    // -------- phase 3: deterministic per-expert partials for aux loss --------
    if (tid < EXP) {
        float ps = 0.f, ct = 0.f;
        for (int t2 = 0; t2 < 128; ++t2) {
            ps += expf(sL[t2 * LPITCH + tid] - m_s[t2]) * is_s[t2];
            ct += (hi_s[t2] == tid ? 1.f : 0.f)
                + ((li_s[t2] == tid && p1_s[t2] > 0.f) ? 1.f : 0.f);
        }
        g_psum[blockIdx.x * EXP + tid] = ps;
        g_cnt [blockIdx.x * EXP + tid] = ct;
    }
}

// ---------------- kernel 2: aux loss (deterministic) ----------------
__global__ void aux_kernel(float* __restrict__ out, int idx) {
    const int e = threadIdx.x;   // 64 threads
    float ps = 0.f, ct = 0.f;
    for (int b = 0; b < NBLK; ++b) {
        ps += g_psum[b * EXP + e];
        ct += g_cnt [b * EXP + e];
    }
    float term = (ct * (1.f / (float)T_TOK)) * (ps * (1.f / (float)T_TOK));
#pragma unroll
    for (int off = 16; off > 0; off >>= 1)
        term += __shfl_xor_sync(0xffffffffu, term, off);
    __shared__ float sm[2];
    if ((e & 31) == 0) sm[e >> 5] = term;
    __syncthreads();
    if (e == 0) out[idx] = (sm[0] + sm[1]) * (float)EXP;
}

extern "C" void kernel_launch(void* const* d_in, const int* in_sizes, int n_in,
                              void* d_out, int out_size) {
    (void)in_sizes; (void)n_in;
    const float* x  = (const float*)d_in[0];   // [16384, 2048]
    const float* rn = (const float*)d_in[1];   // [16384, 64]
    const float* Wg = (const float*)d_in[2];   // [64, 2048]
    const float* bg = (const float*)d_in[3];   // [64]
    const float* Wn = (const float*)d_in[4];   // [64, 2048]
    float* out = (float*)d_out;

    cudaFuncSetAttribute(moe_kernel, cudaFuncAttributeMaxDynamicSharedMemorySize, DYN_BYTES);
    shim1_kernel<<<1, 32>>>();
    shim2_kernel<<<1, 32>>>();
    splitW_kernel<<<1024, 256>>>(Wg, Wn);
    moe_kernel<<<NBLK, THREADS, DYN_BYTES>>>(x, rn, bg, Wg, Wn, out);
    aux_kernel<<<1, EXP>>>(out, out_size - 1);
}